// round 4
// baseline (speedup 1.0000x reference)
#include <cuda_runtime.h>
#include <cuda_bf16.h>
#include <cuda_fp16.h>

#define SRC_LEN 256
#define TRG_LEN 256
#define BATCH   32
#define HID     512
#define ATT     128

// Scratch for projected activations (device globals; no allocation allowed).
// Layout: [(len_idx * BATCH + b) * ATT + a]
__device__ float g_enc_att[SRC_LEN * BATCH * ATT];
__device__ float g_dec_att[TRG_LEN * BATCH * ATT];

typedef unsigned long long u64;
typedef unsigned int u32;

// ---- packed f32x2 helpers (Blackwell FFMA2 path) ----
__device__ __forceinline__ u64 dup2(float x) {
    u64 r; asm("mov.b64 %0, {%1, %1};" : "=l"(r) : "f"(x)); return r;
}
__device__ __forceinline__ void ffma2(u64& d, u64 a, u64 b) {
    asm("fma.rn.f32x2 %0, %1, %2, %0;" : "+l"(d) : "l"(a), "l"(b));
}
__device__ __forceinline__ float2 unpk2(u64 v) {
    float2 r; asm("mov.b64 {%0, %1}, %2;" : "=f"(r.x), "=f"(r.y) : "l"(v)); return r;
}

// ---- fp16x2 helpers ----
__device__ __forceinline__ u32 pack_h2(float lo, float hi) {
    // cvt.rn.f16x2.f32 d, a, b  ->  d.h1 = cvt(a), d.h0 = cvt(b)
    u32 r; asm("cvt.rn.f16x2.f32 %0, %1, %2;" : "=r"(r) : "f"(hi), "f"(lo)); return r;
}
__device__ __forceinline__ u32 tanh_h2(u32 x) {
    u32 y; asm("tanh.approx.f16x2 %0, %1;" : "=r"(y) : "r"(x)); return y;
}
__device__ __forceinline__ u32 hadd2_(u32 a, u32 b) {
    u32 d; asm("add.rn.f16x2 %0, %1, %2;" : "=r"(d) : "r"(a), "r"(b)); return d;
}
__device__ __forceinline__ u32 hfma2_(u32 a, u32 b, u32 c) {
    u32 d; asm("fma.rn.f16x2 %0, %1, %2, %3;" : "=r"(d) : "r"(a), "r"(b), "r"(c)); return d;
}
__device__ __forceinline__ float2 h2_to_f2(u32 h) {
    float2 r;
    asm("{ .reg .f16 lo, hi;\n\t"
        "  mov.b32 {lo, hi}, %2;\n\t"
        "  cvt.f32.f16 %0, lo;\n\t"
        "  cvt.f32.f16 %1, hi; }"
        : "=f"(r.x), "=f"(r.y) : "r"(h));
    return r;
}

// ---------------------------------------------------------------------------
// Projection GEMM: C[row][n] = sum_h X[row][h] * W[n][h]  (+ bias if z==1)
// X: 8192 x 512 row-major, W: 128 x 512 row-major, C: 8192 x 128.
// BM=64, BN=128 (full ATT), BK=32, 256 threads, 4m x 8n per thread.
// Accumulators packed along n (f32x2); B-pairs load free via LDS.128,
// only 4 m-dups per kk. Inner kk: 3 LDS.128 + 4 mov + 16 FFMA2 = 32 MACs.
// grid = (128 m-blocks, 2 [enc|dec])
// ---------------------------------------------------------------------------
__global__ __launch_bounds__(256) void proj_kernel(
    const float* __restrict__ dec_out,
    const float* __restrict__ enc_outs,
    const float* __restrict__ W_s,
    const float* __restrict__ W_t,
    const float* __restrict__ b_t)
{
    const int z = blockIdx.y;
    const float* __restrict__ X = z ? dec_out : enc_outs;
    const float* __restrict__ W = z ? W_t : W_s;
    float* __restrict__ C = z ? g_dec_att : g_enc_att;

    __shared__ float As[32][64];   // [k][m]
    __shared__ float Bs[32][128];  // [k][n]

    const int tid = threadIdx.x;
    const int tx = tid & 15;       // n-group: 8 n each
    const int ty = tid >> 4;       // m-group: 4 m each
    const int m0 = blockIdx.x * 64;

    u64 acc2[4][4];                // [m][n-pair]
    #pragma unroll
    for (int i = 0; i < 4; i++)
        #pragma unroll
        for (int j = 0; j < 4; j++) acc2[i][j] = 0ull;

    for (int k0 = 0; k0 < HID; k0 += 32) {
        // A tile: 64 rows x 32 k = 512 float4, 2 per thread.
        #pragma unroll
        for (int r = 0; r < 2; r++) {
            const int i  = (tid << 1) + r;     // 0..511
            const int m  = i >> 3;
            const int kq = i & 7;
            const float4 va = *reinterpret_cast<const float4*>(
                X + (size_t)(m0 + m) * HID + k0 + (kq << 2));
            As[kq * 4 + 0][m] = va.x;
            As[kq * 4 + 1][m] = va.y;
            As[kq * 4 + 2][m] = va.z;
            As[kq * 4 + 3][m] = va.w;
        }
        // B tile: 128 rows x 32 k = 1024 float4, 4 per thread (2 passes).
        #pragma unroll
        for (int pass = 0; pass < 2; pass++) {
            #pragma unroll
            for (int r = 0; r < 2; r++) {
                const int i  = (tid << 1) + r;
                const int n  = pass * 64 + (i >> 3);
                const int kq = i & 7;
                const float4 vb = *reinterpret_cast<const float4*>(
                    W + (size_t)n * HID + k0 + (kq << 2));
                Bs[kq * 4 + 0][n] = vb.x;
                Bs[kq * 4 + 1][n] = vb.y;
                Bs[kq * 4 + 2][n] = vb.z;
                Bs[kq * 4 + 3][n] = vb.w;
            }
        }
        __syncthreads();

        #pragma unroll
        for (int kk = 0; kk < 32; kk++) {
            const float4 av = *reinterpret_cast<const float4*>(&As[kk][ty << 2]);
            const ulonglong2 b01 = *reinterpret_cast<const ulonglong2*>(&Bs[kk][tx << 3]);
            const ulonglong2 b23 = *reinterpret_cast<const ulonglong2*>(&Bs[kk][(tx << 3) + 4]);
            const u64 ad0 = dup2(av.x);
            const u64 ad1 = dup2(av.y);
            const u64 ad2 = dup2(av.z);
            const u64 ad3 = dup2(av.w);
            ffma2(acc2[0][0], ad0, b01.x); ffma2(acc2[0][1], ad0, b01.y);
            ffma2(acc2[0][2], ad0, b23.x); ffma2(acc2[0][3], ad0, b23.y);
            ffma2(acc2[1][0], ad1, b01.x); ffma2(acc2[1][1], ad1, b01.y);
            ffma2(acc2[1][2], ad1, b23.x); ffma2(acc2[1][3], ad1, b23.y);
            ffma2(acc2[2][0], ad2, b01.x); ffma2(acc2[2][1], ad2, b01.y);
            ffma2(acc2[2][2], ad2, b23.x); ffma2(acc2[2][3], ad2, b23.y);
            ffma2(acc2[3][0], ad3, b01.x); ffma2(acc2[3][1], ad3, b01.y);
            ffma2(acc2[3][2], ad3, b23.x); ffma2(acc2[3][3], ad3, b23.y);
        }
        __syncthreads();
    }

    // Epilogue: unpack to c[4][8], bias for dec, two float4 stores per m-row.
    float bias[8];
    #pragma unroll
    for (int j = 0; j < 8; j++) bias[j] = 0.f;
    if (z) {
        #pragma unroll
        for (int j = 0; j < 8; j++) bias[j] = b_t[(tx << 3) + j];
    }
    #pragma unroll
    for (int i = 0; i < 4; i++) {
        float c[8];
        #pragma unroll
        for (int j = 0; j < 4; j++) {
            const float2 t = unpk2(acc2[i][j]);
            c[2 * j]     = t.x + bias[2 * j];
            c[2 * j + 1] = t.y + bias[2 * j + 1];
        }
        float* cp = C + (size_t)(m0 + (ty << 2) + i) * ATT + (tx << 3);
        float4 o0; o0.x = c[0]; o0.y = c[1]; o0.z = c[2]; o0.w = c[3];
        float4 o1; o1.x = c[4]; o1.y = c[5]; o1.z = c[6]; o1.w = c[7];
        *reinterpret_cast<float4*>(cp) = o0;
        *reinterpret_cast<float4*>(cp + 4) = o1;
    }
}

// ---------------------------------------------------------------------------
// Score kernel: out[t][b][s] = sum_a v[a] * tanh(dec_att[t,b,a] + enc_att[s,b,a])
// Block tile: 32 t x 64 s, one b. 128 threads, 4t x 4s per thread.
// Tiles pre-converted to fp16x2 in SMEM at fill time:
//   sh_e2[a][s/2] = (e_s, e_{s+1})   packed s-pairs
//   sh_d2[a][t]   = (d_t, d_t)       dup'd
//   sh_v2[a]      = (v_a, v_a)       dup'd
// Inner loop per a: 3 LDS + 8 HADD2 + 8 tanh.f16x2 + 8 HFMA2 (16 elements).
// fp16 chunk accumulators flushed to f32 every 4 a-steps.
// grid = (SRC/64 = 4, TRG/32 = 8, BATCH = 32)
// ---------------------------------------------------------------------------
__global__ __launch_bounds__(128) void score_kernel(
    const float* __restrict__ v_a,
    float* __restrict__ out)
{
    __shared__ u32 sh_e2[ATT][32];   // [a][s-pair]
    __shared__ u32 sh_d2[ATT][32];   // [a][t] dup'd
    __shared__ u32 sh_v2[ATT];

    const int tid = threadIdx.x;
    const int b = blockIdx.z;
    const int s_base = blockIdx.x * 64;
    const int t_base = blockIdx.y * 32;

    // Fill e: 1024 pair-units (32 s-pairs x 32 a-chunks), 8 per thread.
    for (int u = tid; u < 1024; u += 128) {
        const int us = u & 31;       // s-pair index
        const int a4 = u >> 5;       // a-chunk (float4)
        const float* p = g_enc_att +
            ((size_t)(s_base + 2 * us) * BATCH + b) * ATT + (a4 << 2);
        const float4 va = *reinterpret_cast<const float4*>(p);
        const float4 vb = *reinterpret_cast<const float4*>(p + (size_t)BATCH * ATT);
        sh_e2[a4 * 4 + 0][us] = pack_h2(va.x, vb.x);
        sh_e2[a4 * 4 + 1][us] = pack_h2(va.y, vb.y);
        sh_e2[a4 * 4 + 2][us] = pack_h2(va.z, vb.z);
        sh_e2[a4 * 4 + 3][us] = pack_h2(va.w, vb.w);
    }
    // Fill d (dup'd): 1024 float4 units, 8 per thread.
    for (int u = tid; u < 1024; u += 128) {
        const int t  = u & 31;
        const int a4 = u >> 5;
        const float4 dv = *reinterpret_cast<const float4*>(
            g_dec_att + ((size_t)(t_base + t) * BATCH + b) * ATT + (a4 << 2));
        sh_d2[a4 * 4 + 0][t] = pack_h2(dv.x, dv.x);
        sh_d2[a4 * 4 + 1][t] = pack_h2(dv.y, dv.y);
        sh_d2[a4 * 4 + 2][t] = pack_h2(dv.z, dv.z);
        sh_d2[a4 * 4 + 3][t] = pack_h2(dv.w, dv.w);
    }
    if (tid < ATT) {
        const float v = v_a[tid];
        sh_v2[tid] = pack_h2(v, v);
    }
    __syncthreads();

    const int tx = tid & 15;        // s-group: 2 pairs (4 s)
    const int ty = tid >> 4;        // t-group: 4 t  (0..7)

    float acc[4][4];
    #pragma unroll
    for (int i = 0; i < 4; i++)
        #pragma unroll
        for (int j = 0; j < 4; j++) acc[i][j] = 0.f;

    #pragma unroll 2
    for (int ac = 0; ac < ATT; ac += 4) {
        u32 ah[4][2];
        #pragma unroll
        for (int i = 0; i < 4; i++) { ah[i][0] = 0u; ah[i][1] = 0u; }

        #pragma unroll
        for (int k = 0; k < 4; k++) {
            const int a = ac + k;
            const uint2 e = *reinterpret_cast<const uint2*>(&sh_e2[a][tx << 1]);
            const uint4 dd = *reinterpret_cast<const uint4*>(&sh_d2[a][ty << 2]);
            const u32 v2 = sh_v2[a];
            const u32 d[4] = {dd.x, dd.y, dd.z, dd.w};
            #pragma unroll
            for (int i = 0; i < 4; i++) {
                const u32 t0 = tanh_h2(hadd2_(d[i], e.x));
                const u32 t1 = tanh_h2(hadd2_(d[i], e.y));
                ah[i][0] = hfma2_(v2, t0, ah[i][0]);
                ah[i][1] = hfma2_(v2, t1, ah[i][1]);
            }
        }
        #pragma unroll
        for (int i = 0; i < 4; i++) {
            const float2 f0 = h2_to_f2(ah[i][0]);
            const float2 f1 = h2_to_f2(ah[i][1]);
            acc[i][0] += f0.x; acc[i][1] += f0.y;
            acc[i][2] += f1.x; acc[i][3] += f1.y;
        }
    }

    // Store: 4 t-rows x float4 of s.
    #pragma unroll
    for (int i = 0; i < 4; i++) {
        const int tg = t_base + (ty << 2) + i;
        float* op = out + ((size_t)tg * BATCH + b) * SRC_LEN + s_base + (tx << 2);
        float4 o; o.x = acc[i][0]; o.y = acc[i][1]; o.z = acc[i][2]; o.w = acc[i][3];
        *reinterpret_cast<float4*>(op) = o;
    }
}

extern "C" void kernel_launch(void* const* d_in, const int* in_sizes, int n_in,
                              void* d_out, int out_size)
{
    const float* dec_out  = (const float*)d_in[0];  // (256, 32, 512)
    const float* enc_outs = (const float*)d_in[1];  // (256, 32, 512)
    const float* W_s      = (const float*)d_in[2];  // (128, 512)
    const float* W_t      = (const float*)d_in[3];  // (128, 512)
    const float* b_t      = (const float*)d_in[4];  // (128,)
    const float* v_a      = (const float*)d_in[5];  // (128, 1)
    float* out = (float*)d_out;                     // (256, 32, 256)

    (void)in_sizes; (void)n_in; (void)out_size;

    proj_kernel<<<dim3(128, 2), 256>>>(dec_out, enc_outs, W_s, W_t, b_t);
    score_kernel<<<dim3(SRC_LEN / 64, TRG_LEN / 32, BATCH), 128>>>(v_a, out);
}

// round 5
// speedup vs baseline: 1.8960x; 1.8960x over previous
#include <cuda_runtime.h>
#include <cuda_bf16.h>
#include <cuda_fp16.h>

#define SRC_LEN 256
#define TRG_LEN 256
#define BATCH   32
#define HID     512
#define ATT     128

// Scratch for projected activations (device globals; no allocation allowed).
// Layout: [(len_idx * BATCH + b) * ATT + a]
__device__ float g_enc_att[SRC_LEN * BATCH * ATT];
__device__ float g_dec_att[TRG_LEN * BATCH * ATT];

typedef unsigned int u32;

// ---- fp16x2 helpers ----
__device__ __forceinline__ u32 pack_h2(float lo, float hi) {
    // cvt.rn.f16x2.f32 d, a, b  ->  d.h1 = cvt(a), d.h0 = cvt(b)
    u32 r; asm("cvt.rn.f16x2.f32 %0, %1, %2;" : "=r"(r) : "f"(hi), "f"(lo)); return r;
}
__device__ __forceinline__ u32 tanh_h2(u32 x) {
    u32 y; asm("tanh.approx.f16x2 %0, %1;" : "=r"(y) : "r"(x)); return y;
}
__device__ __forceinline__ u32 hadd2_(u32 a, u32 b) {
    u32 d; asm("add.rn.f16x2 %0, %1, %2;" : "=r"(d) : "r"(a), "r"(b)); return d;
}
__device__ __forceinline__ u32 hfma2_(u32 a, u32 b, u32 c) {
    u32 d; asm("fma.rn.f16x2 %0, %1, %2, %3;" : "=r"(d) : "r"(a), "r"(b), "r"(c)); return d;
}
__device__ __forceinline__ float2 h2_to_f2(u32 h) {
    float2 r;
    asm("{ .reg .f16 lo, hi;\n\t"
        "  mov.b32 {lo, hi}, %2;\n\t"
        "  cvt.f32.f16 %0, lo;\n\t"
        "  cvt.f32.f16 %1, hi; }"
        : "=f"(r.x), "=f"(r.y) : "r"(h));
    return r;
}

// ---------------------------------------------------------------------------
// Projection GEMM (R2 version, measured 79.5us — at 80% of scalar FFMA roofline):
// C[row][n] = sum_h X[row][h] * W[n][h]  (+ bias if z==1)
// X: 8192 x 512 row-major, W: 128 x 512 row-major, C: 8192 x 128.
// BM=64, BN=64, BK=32, 256 threads, 4x4 register tile per thread.
// grid = (128, 2, 2 [enc|dec])
// ---------------------------------------------------------------------------
__global__ __launch_bounds__(256) void proj_kernel(
    const float* __restrict__ dec_out,
    const float* __restrict__ enc_outs,
    const float* __restrict__ W_s,
    const float* __restrict__ W_t,
    const float* __restrict__ b_t)
{
    const int z = blockIdx.z;
    const float* __restrict__ X = z ? dec_out : enc_outs;
    const float* __restrict__ W = z ? W_t : W_s;
    float* __restrict__ C = z ? g_dec_att : g_enc_att;

    __shared__ float As[32][64];  // [k][m]
    __shared__ float Bs[32][64];  // [k][n]

    const int tid = threadIdx.x;
    const int tx = tid & 15;       // n-dim thread
    const int ty = tid >> 4;       // m-dim thread
    const int m0 = blockIdx.x * 64;
    const int n0 = blockIdx.y * 64;

    float acc[4][4];
    #pragma unroll
    for (int i = 0; i < 4; i++)
        #pragma unroll
        for (int j = 0; j < 4; j++) acc[i][j] = 0.f;

    for (int k0 = 0; k0 < HID; k0 += 32) {
        #pragma unroll
        for (int r = 0; r < 2; r++) {
            const int i  = (tid << 1) + r;     // 0..511
            const int m  = i >> 3;
            const int kq = i & 7;
            const float4 va = *reinterpret_cast<const float4*>(
                X + (size_t)(m0 + m) * HID + k0 + (kq << 2));
            As[kq * 4 + 0][m] = va.x;
            As[kq * 4 + 1][m] = va.y;
            As[kq * 4 + 2][m] = va.z;
            As[kq * 4 + 3][m] = va.w;
            const float4 vb = *reinterpret_cast<const float4*>(
                W + (size_t)(n0 + m) * HID + k0 + (kq << 2));
            Bs[kq * 4 + 0][m] = vb.x;
            Bs[kq * 4 + 1][m] = vb.y;
            Bs[kq * 4 + 2][m] = vb.z;
            Bs[kq * 4 + 3][m] = vb.w;
        }
        __syncthreads();

        #pragma unroll
        for (int kk = 0; kk < 32; kk++) {
            const float4 av = *reinterpret_cast<const float4*>(&As[kk][ty << 2]);
            const float4 bv = *reinterpret_cast<const float4*>(&Bs[kk][tx << 2]);
            const float a[4] = {av.x, av.y, av.z, av.w};
            const float b[4] = {bv.x, bv.y, bv.z, bv.w};
            #pragma unroll
            for (int i = 0; i < 4; i++)
                #pragma unroll
                for (int j = 0; j < 4; j++)
                    acc[i][j] = fmaf(a[i], b[j], acc[i][j]);
        }
        __syncthreads();
    }

    float bias[4] = {0.f, 0.f, 0.f, 0.f};
    if (z) {
        #pragma unroll
        for (int j = 0; j < 4; j++) bias[j] = b_t[n0 + (tx << 2) + j];
    }
    #pragma unroll
    for (int i = 0; i < 4; i++) {
        float4 o;
        o.x = acc[i][0] + bias[0];
        o.y = acc[i][1] + bias[1];
        o.z = acc[i][2] + bias[2];
        o.w = acc[i][3] + bias[3];
        *reinterpret_cast<float4*>(
            C + (size_t)(m0 + (ty << 2) + i) * ATT + n0 + (tx << 2)) = o;
    }
}

// ---------------------------------------------------------------------------
// Score kernel: out[t][b][s] = sum_a v[a] * tanh(dec_att[t,b,a] + enc_att[s,b,a])
// Block tile: 32 t x 32 s, one b. 256 threads, 2t x 2s per thread.
// SMEM prepacked fp16x2 with a INNERMOST (uint4 LDS covers 4 a-steps):
//   sh_e[p][a] = (e[2p], e[2p+1]) at att index a      (s-pair packed)
//   sh_d[t][a] = (d[t], d[t])                          (dup'd)
//   sh_v[a]    = (v_a, v_a)                            (dup'd)
// Rows padded to 132 u32 -> conflict-free / broadcast LDS.128.
// Inner 4-a iter: 4 LDS.128 + 8 HADD2 + 8 tanh.f16x2 + 8 HFMA2 + flush.
// grid = (SRC/32 = 8, TRG/32 = 8, BATCH = 32)
// ---------------------------------------------------------------------------
#define ROW 132

__global__ __launch_bounds__(256) void score_kernel(
    const float* __restrict__ v_a,
    float* __restrict__ out)
{
    __shared__ u32 sh_e[16][ROW];   // [s-pair][a]
    __shared__ u32 sh_d[32][ROW];   // [t][a] dup'd
    __shared__ u32 sh_v[ROW];       // [a] dup'd

    const int tid = threadIdx.x;
    const int b = blockIdx.z;
    const int s_base = blockIdx.x * 32;
    const int t_base = blockIdx.y * 32;

    // Fill e: 16 s-pairs x 32 a-chunks = 512 units, 2 per thread.
    #pragma unroll
    for (int r = 0; r < 2; r++) {
        const int u  = tid + r * 256;
        const int p  = u & 15;        // s-pair
        const int a4 = u >> 4;        // a-chunk (float4)
        const float* q = g_enc_att +
            ((size_t)(s_base + 2 * p) * BATCH + b) * ATT + (a4 << 2);
        const float4 va = *reinterpret_cast<const float4*>(q);
        const float4 vb = *reinterpret_cast<const float4*>(q + (size_t)BATCH * ATT);
        sh_e[p][a4 * 4 + 0] = pack_h2(va.x, vb.x);
        sh_e[p][a4 * 4 + 1] = pack_h2(va.y, vb.y);
        sh_e[p][a4 * 4 + 2] = pack_h2(va.z, vb.z);
        sh_e[p][a4 * 4 + 3] = pack_h2(va.w, vb.w);
    }
    // Fill d (dup'd): 32 t x 32 a-chunks = 1024 units, 4 per thread.
    #pragma unroll
    for (int r = 0; r < 4; r++) {
        const int u  = tid + r * 256;
        const int t  = u & 31;
        const int a4 = u >> 5;
        const float4 dv = *reinterpret_cast<const float4*>(
            g_dec_att + ((size_t)(t_base + t) * BATCH + b) * ATT + (a4 << 2));
        sh_d[t][a4 * 4 + 0] = pack_h2(dv.x, dv.x);
        sh_d[t][a4 * 4 + 1] = pack_h2(dv.y, dv.y);
        sh_d[t][a4 * 4 + 2] = pack_h2(dv.z, dv.z);
        sh_d[t][a4 * 4 + 3] = pack_h2(dv.w, dv.w);
    }
    // Fill v (dup'd): 32 chunks.
    if (tid < 32) {
        const float4 vv = *reinterpret_cast<const float4*>(v_a + (tid << 2));
        sh_v[tid * 4 + 0] = pack_h2(vv.x, vv.x);
        sh_v[tid * 4 + 1] = pack_h2(vv.y, vv.y);
        sh_v[tid * 4 + 2] = pack_h2(vv.z, vv.z);
        sh_v[tid * 4 + 3] = pack_h2(vv.w, vv.w);
    }
    __syncthreads();

    const int tx = tid & 15;        // s-pair index (2 s)
    const int ty = tid >> 4;        // t-pair group: t = 2*ty, 2*ty+1

    float acc00 = 0.f, acc01 = 0.f, acc10 = 0.f, acc11 = 0.f;

    for (int a = 0; a < ATT; a += 4) {
        const uint4 e  = *reinterpret_cast<const uint4*>(&sh_e[tx][a]);
        const uint4 dA = *reinterpret_cast<const uint4*>(&sh_d[2 * ty][a]);
        const uint4 dB = *reinterpret_cast<const uint4*>(&sh_d[2 * ty + 1][a]);
        const uint4 vv = *reinterpret_cast<const uint4*>(&sh_v[a]);

        u32 ah0 = 0u, ah1 = 0u;   // fp16x2 chunk accumulators (t0 / t1)
        const u32 ev[4] = {e.x, e.y, e.z, e.w};
        const u32 da[4] = {dA.x, dA.y, dA.z, dA.w};
        const u32 db[4] = {dB.x, dB.y, dB.z, dB.w};
        const u32 vz[4] = {vv.x, vv.y, vv.z, vv.w};
        #pragma unroll
        for (int k = 0; k < 4; k++) {
            const u32 t0 = tanh_h2(hadd2_(da[k], ev[k]));
            const u32 t1 = tanh_h2(hadd2_(db[k], ev[k]));
            ah0 = hfma2_(vz[k], t0, ah0);
            ah1 = hfma2_(vz[k], t1, ah1);
        }
        const float2 f0 = h2_to_f2(ah0);
        const float2 f1 = h2_to_f2(ah1);
        acc00 += f0.x; acc01 += f0.y;   // t = 2ty,   s = 2tx, 2tx+1
        acc10 += f1.x; acc11 += f1.y;   // t = 2ty+1
    }

    const int tg = t_base + 2 * ty;
    const int sg = s_base + 2 * tx;
    float* o0 = out + ((size_t)tg * BATCH + b) * SRC_LEN + sg;
    float2 r0; r0.x = acc00; r0.y = acc01;
    *reinterpret_cast<float2*>(o0) = r0;
    float* o1 = o0 + (size_t)BATCH * SRC_LEN;   // t+1
    float2 r1; r1.x = acc10; r1.y = acc11;
    *reinterpret_cast<float2*>(o1) = r1;
}

extern "C" void kernel_launch(void* const* d_in, const int* in_sizes, int n_in,
                              void* d_out, int out_size)
{
    const float* dec_out  = (const float*)d_in[0];  // (256, 32, 512)
    const float* enc_outs = (const float*)d_in[1];  // (256, 32, 512)
    const float* W_s      = (const float*)d_in[2];  // (128, 512)
    const float* W_t      = (const float*)d_in[3];  // (128, 512)
    const float* b_t      = (const float*)d_in[4];  // (128,)
    const float* v_a      = (const float*)d_in[5];  // (128, 1)
    float* out = (float*)d_out;                     // (256, 32, 256)

    (void)in_sizes; (void)n_in; (void)out_size;

    proj_kernel<<<dim3(128, 2, 2), 256>>>(dec_out, enc_outs, W_s, W_t, b_t);
    score_kernel<<<dim3(SRC_LEN / 32, TRG_LEN / 32, BATCH), 256>>>(v_a, out);
}

// round 7
// speedup vs baseline: 2.8001x; 1.4768x over previous
#include <cuda_runtime.h>
#include <cuda_bf16.h>
#include <cuda_fp16.h>
#include <cstdint>

#define SRC_LEN 256
#define TRG_LEN 256
#define BATCH   32
#define HID     512
#define ATT     128

// Scratch for projected activations. Layout: [(len_idx * BATCH + b) * ATT + a]
__device__ float g_enc_att[SRC_LEN * BATCH * ATT];
__device__ float g_dec_att[TRG_LEN * BATCH * ATT];

typedef unsigned int u32;
typedef unsigned long long u64;

__device__ __forceinline__ u32 smem_u32(const void* p) {
    u32 a; asm("{ .reg .u64 t; cvta.to.shared.u64 t, %1; cvt.u32.u64 %0, t; }"
               : "=r"(a) : "l"(p));
    return a;
}

#define SWZ128(off) ((off) ^ (((off) >> 3) & 0x70))

#define LDSM_X4(rr, addr) \
    asm volatile("ldmatrix.sync.aligned.m8n8.x4.shared.b16 {%0,%1,%2,%3}, [%4];" \
        : "=r"((rr)[0]), "=r"((rr)[1]), "=r"((rr)[2]), "=r"((rr)[3]) : "r"(addr))

__device__ __forceinline__ void mma16816(float* d, const u32* a, const u32* b) {
    asm volatile(
        "mma.sync.aligned.m16n8k16.row.col.f32.bf16.bf16.f32 "
        "{%0,%1,%2,%3}, {%4,%5,%6,%7}, {%8,%9}, {%0,%1,%2,%3};"
        : "+f"(d[0]), "+f"(d[1]), "+f"(d[2]), "+f"(d[3])
        : "r"(a[0]), "r"(a[1]), "r"(a[2]), "r"(a[3]), "r"(b[0]), "r"(b[1]));
}

// fp32 -> bf16 hi (truncate) + bf16 lo (residual), 4 lanes packed into u64s.
__device__ __forceinline__ void split_pack4(const float4 v, u64& hi64, u64& lo64) {
    u32 hb[4], lb[4];
    const float x[4] = {v.x, v.y, v.z, v.w};
    #pragma unroll
    for (int jj = 0; jj < 4; jj++) {
        const u32 xb = __float_as_uint(x[jj]);
        hb[jj] = xb >> 16;
        const float hf = __uint_as_float(xb & 0xFFFF0000u);
        const __nv_bfloat16 lo = __float2bfloat16(x[jj] - hf);
        lb[jj] = (u32)*reinterpret_cast<const unsigned short*>(&lo);
    }
    hi64 = (u64)(hb[0] | (hb[1] << 16)) | ((u64)(hb[2] | (hb[3] << 16)) << 32);
    lo64 = (u64)(lb[0] | (lb[1] << 16)) | ((u64)(lb[2] | (lb[3] << 16)) << 32);
}

// =====================================================================
// HMMA projection: C[m][n] = sum_h X[m][h] * W[n][h]  (+ bias if z)
// CTA: 128 m x 128 n (full ATT); K-chunks of 64; bf16 hi/lo split, 3 passes.
// 8 warps = 4m x 2n, warp tile 32x64, mma.m16n8k16.
// SMEM (dynamic 64KB): A_hi, A_lo, B_hi, B_lo each 128x64 bf16 SW128-swizzled.
// grid = (64 m-tiles, 2 [enc|dec]), 256 threads.
// =====================================================================
#define PSM_AH 0
#define PSM_AL 16384
#define PSM_BH 32768
#define PSM_BL 49152
#define PSM_TOTAL 65536

__global__ __launch_bounds__(256) void proj_mma_kernel(
    const float* __restrict__ dec_out,
    const float* __restrict__ enc_outs,
    const float* __restrict__ W_s,
    const float* __restrict__ W_t,
    const float* __restrict__ b_t)
{
    extern __shared__ char smem[];
    const u32 sb = smem_u32(smem);
    const u32 AHs = sb + PSM_AH, ALs = sb + PSM_AL;
    const u32 BHs = sb + PSM_BH, BLs = sb + PSM_BL;

    const int tid = threadIdx.x;
    const int wid = tid >> 5;
    const int lane = tid & 31;
    const int z = blockIdx.y;
    const float* __restrict__ X = z ? dec_out : enc_outs;
    const float* __restrict__ W = z ? W_t : W_s;
    float* __restrict__ C = z ? g_dec_att : g_enc_att;
    const int m0 = blockIdx.x * 128;

    // ldmatrix lane geometry
    const int j = lane >> 3;           // matrix index 0..3
    const int r = lane & 7;            // row within 8x8
    const int wm = wid & 3;            // m-group (x32)
    const int wn = wid >> 2;           // n-group (x64)

    // A-frag rows: mat j -> row offset (j&1)*8, k offset (j>>1)*8
    const int rowA0 = wm * 32 + ((j & 1) << 3) + r;      // mf = 0
    const int rowA1 = rowA0 + 16;                         // mf = 1
    const u32 offA0 = rowA0 * 128, cxA0 = (rowA0 & 7) * 16;
    const u32 offA1 = rowA1 * 128, cxA1 = (rowA1 & 7) * 16;
    const u32 kbAj = (u32)((j >> 1) << 4);               // k-byte from j

    // B-frag rows per pair p: mat j -> n offset (j>>1)*8, k offset (j&1)*8
    u32 offB[4], cxB[4];
    #pragma unroll
    for (int p = 0; p < 4; p++) {
        const int nrow = wn * 64 + p * 16 + ((j >> 1) << 3) + r;
        offB[p] = nrow * 128;
        cxB[p]  = (nrow & 7) * 16;
    }
    const u32 kbBj = (u32)((j & 1) << 4);

    float d[2][8][4];
    #pragma unroll
    for (int mf = 0; mf < 2; mf++)
        #pragma unroll
        for (int nf = 0; nf < 8; nf++)
            #pragma unroll
            for (int q = 0; q < 4; q++) d[mf][nf][q] = 0.f;

    for (int c = 0; c < 8; c++) {
        const int k0 = c * 64;
        __syncthreads();   // previous chunk's ldmatrix done before refill

        // Fill A tiles: 128 rows x 16 float4 = 2048 units, 8 per thread.
        for (int u = tid; u < 2048; u += 256) {
            const int row = u >> 4;
            const int q = u & 15;
            const float4 v = *reinterpret_cast<const float4*>(
                X + (size_t)(m0 + row) * HID + k0 + (q << 2));
            u64 h, l; split_pack4(v, h, l);
            const u32 sw = SWZ128((u32)(row * 128 + (q << 3)));
            *reinterpret_cast<u64*>(smem + PSM_AH + sw) = h;
            *reinterpret_cast<u64*>(smem + PSM_AL + sw) = l;
        }
        // Fill B tiles: 128 W-rows x 16 float4.
        for (int u = tid; u < 2048; u += 256) {
            const int row = u >> 4;
            const int q = u & 15;
            const float4 v = *reinterpret_cast<const float4*>(
                W + (size_t)row * HID + k0 + (q << 2));
            u64 h, l; split_pack4(v, h, l);
            const u32 sw = SWZ128((u32)(row * 128 + (q << 3)));
            *reinterpret_cast<u64*>(smem + PSM_BH + sw) = h;
            *reinterpret_cast<u64*>(smem + PSM_BL + sw) = l;
        }
        __syncthreads();

        #pragma unroll
        for (int kk = 0; kk < 4; kk++) {
            const u32 kbA = (u32)(kk * 32) + kbAj;
            const u32 kbB = (u32)(kk * 32) + kbBj;

            u32 ah0[4], ah1[4], al0[4], al1[4];
            LDSM_X4(ah0, AHs + offA0 + (kbA ^ cxA0));
            LDSM_X4(ah1, AHs + offA1 + (kbA ^ cxA1));
            LDSM_X4(al0, ALs + offA0 + (kbA ^ cxA0));
            LDSM_X4(al1, ALs + offA1 + (kbA ^ cxA1));

            u32 bb[4][4];
            #pragma unroll
            for (int p = 0; p < 4; p++)
                LDSM_X4(bb[p], BHs + offB[p] + (kbB ^ cxB[p]));
            #pragma unroll
            for (int p = 0; p < 4; p++) {
                // hh pass
                mma16816(d[0][2 * p],     ah0, &bb[p][0]);
                mma16816(d[0][2 * p + 1], ah0, &bb[p][2]);
                mma16816(d[1][2 * p],     ah1, &bb[p][0]);
                mma16816(d[1][2 * p + 1], ah1, &bb[p][2]);
                // lh pass (A_lo x B_hi)
                mma16816(d[0][2 * p],     al0, &bb[p][0]);
                mma16816(d[0][2 * p + 1], al0, &bb[p][2]);
                mma16816(d[1][2 * p],     al1, &bb[p][0]);
                mma16816(d[1][2 * p + 1], al1, &bb[p][2]);
            }
            #pragma unroll
            for (int p = 0; p < 4; p++)
                LDSM_X4(bb[p], BLs + offB[p] + (kbB ^ cxB[p]));
            #pragma unroll
            for (int p = 0; p < 4; p++) {
                // hl pass (A_hi x B_lo)
                mma16816(d[0][2 * p],     ah0, &bb[p][0]);
                mma16816(d[0][2 * p + 1], ah0, &bb[p][2]);
                mma16816(d[1][2 * p],     ah1, &bb[p][0]);
                mma16816(d[1][2 * p + 1], ah1, &bb[p][2]);
            }
        }
    }

    // Epilogue: C frag (m16n8): c0,c1 -> row = lane/4, cols (lane%4)*2 +{0,1};
    // c2,c3 -> row+8. Add bias for dec, float2 stores.
    const int er = lane >> 2;
    const int ec = (lane & 3) << 1;
    float bias[8][2];
    #pragma unroll
    for (int nf = 0; nf < 8; nf++) {
        const int col = wn * 64 + nf * 8 + ec;
        bias[nf][0] = z ? b_t[col] : 0.f;
        bias[nf][1] = z ? b_t[col + 1] : 0.f;
    }
    #pragma unroll
    for (int mf = 0; mf < 2; mf++) {
        const int row = m0 + wm * 32 + mf * 16 + er;
        #pragma unroll
        for (int nf = 0; nf < 8; nf++) {
            const int col = wn * 64 + nf * 8 + ec;
            float2 v0; v0.x = d[mf][nf][0] + bias[nf][0]; v0.y = d[mf][nf][1] + bias[nf][1];
            *reinterpret_cast<float2*>(C + (size_t)row * ATT + col) = v0;
            float2 v1; v1.x = d[mf][nf][2] + bias[nf][0]; v1.y = d[mf][nf][3] + bias[nf][1];
            *reinterpret_cast<float2*>(C + (size_t)(row + 8) * ATT + col) = v1;
        }
    }
}

// =====================================================================
// Score kernel (R2 f32 version — fastest measured, at MUFU roofline):
// out[t][b][s] = sum_a v[a] * tanh(dec_att[t,b,a] + enc_att[s,b,a])
// =====================================================================
__device__ __forceinline__ float tanh_fast(float x) {
    float y;
    asm("tanh.approx.f32 %0, %1;" : "=f"(y) : "f"(x));
    return y;
}

__global__ __launch_bounds__(256) void score_kernel(
    const float* __restrict__ v_a,
    float* __restrict__ out)
{
    __shared__ float sh_e[ATT][33];
    __shared__ float sh_d[ATT][33];
    __shared__ float sh_v[ATT];

    const int tid = threadIdx.x;
    const int b = blockIdx.z;
    const int s_base = blockIdx.x * 32;
    const int t_base = blockIdx.y * 32;

    for (int idx = tid; idx < 32 * 32; idx += 256) {
        const int i  = idx >> 5;
        const int a4 = idx & 31;
        const float4 ev = *reinterpret_cast<const float4*>(
            g_enc_att + ((size_t)(s_base + i) * BATCH + b) * ATT + (a4 << 2));
        sh_e[a4 * 4 + 0][i] = ev.x;
        sh_e[a4 * 4 + 1][i] = ev.y;
        sh_e[a4 * 4 + 2][i] = ev.z;
        sh_e[a4 * 4 + 3][i] = ev.w;
        const float4 dv = *reinterpret_cast<const float4*>(
            g_dec_att + ((size_t)(t_base + i) * BATCH + b) * ATT + (a4 << 2));
        sh_d[a4 * 4 + 0][i] = dv.x;
        sh_d[a4 * 4 + 1][i] = dv.y;
        sh_d[a4 * 4 + 2][i] = dv.z;
        sh_d[a4 * 4 + 3][i] = dv.w;
    }
    if (tid < ATT) sh_v[tid] = v_a[tid];
    __syncthreads();

    const int tx = tid & 15;
    const int ty = tid >> 4;
    const int sl = tx << 1;
    const int tl = ty << 1;

    float acc00 = 0.f, acc01 = 0.f, acc10 = 0.f, acc11 = 0.f;

    #pragma unroll 4
    for (int a = 0; a < ATT; a++) {
        const float va = sh_v[a];
        const float e0 = sh_e[a][sl];
        const float e1 = sh_e[a][sl + 1];
        const float d0 = sh_d[a][tl];
        const float d1 = sh_d[a][tl + 1];
        acc00 = fmaf(va, tanh_fast(d0 + e0), acc00);
        acc01 = fmaf(va, tanh_fast(d0 + e1), acc01);
        acc10 = fmaf(va, tanh_fast(d1 + e0), acc10);
        acc11 = fmaf(va, tanh_fast(d1 + e1), acc11);
    }

    const int tg = t_base + tl;
    const int sg = s_base + sl;
    float* o0 = out + ((size_t)tg * BATCH + b) * SRC_LEN + sg;
    float2 r0; r0.x = acc00; r0.y = acc01;
    *reinterpret_cast<float2*>(o0) = r0;
    float* o1 = o0 + (size_t)BATCH * SRC_LEN;
    float2 r1; r1.x = acc10; r1.y = acc11;
    *reinterpret_cast<float2*>(o1) = r1;
}

extern "C" void kernel_launch(void* const* d_in, const int* in_sizes, int n_in,
                              void* d_out, int out_size)
{
    const float* dec_out  = (const float*)d_in[0];  // (256, 32, 512)
    const float* enc_outs = (const float*)d_in[1];  // (256, 32, 512)
    const float* W_s      = (const float*)d_in[2];  // (128, 512)
    const float* W_t      = (const float*)d_in[3];  // (128, 512)
    const float* b_t      = (const float*)d_in[4];  // (128,)
    const float* v_a      = (const float*)d_in[5];  // (128, 1)
    float* out = (float*)d_out;                     // (256, 32, 256)

    (void)in_sizes; (void)n_in; (void)out_size;

    static bool attr_set = false;
    if (!attr_set) {
        cudaFuncSetAttribute(proj_mma_kernel,
                             cudaFuncAttributeMaxDynamicSharedMemorySize, PSM_TOTAL);
        attr_set = true;
    }
    proj_mma_kernel<<<dim3(64, 2), 256, PSM_TOTAL>>>(dec_out, enc_outs, W_s, W_t, b_t);
    score_kernel<<<dim3(SRC_LEN / 32, TRG_LEN / 32, BATCH), 256>>>(v_a, out);
}

// round 8
// speedup vs baseline: 3.1228x; 1.1152x over previous
#include <cuda_runtime.h>
#include <cuda_bf16.h>
#include <cuda_fp16.h>
#include <cstdint>

#define SRC_LEN 256
#define TRG_LEN 256
#define BATCH   32
#define HID     512
#define ATT     128

// Scratch for projected activations. Layout: [(len_idx * BATCH + b) * ATT + a]
__device__ float g_enc_att[SRC_LEN * BATCH * ATT];
__device__ float g_dec_att[TRG_LEN * BATCH * ATT];

// Precomputed, pre-swizzled bf16 hi/lo W tiles: [z][chunk][16KB tile]
__device__ __align__(16) unsigned char g_wh[2][8][16384];
__device__ __align__(16) unsigned char g_wl[2][8][16384];

typedef unsigned int u32;
typedef unsigned long long u64;

__device__ __forceinline__ u32 smem_u32(const void* p) {
    u32 a; asm("{ .reg .u64 t; cvta.to.shared.u64 t, %1; cvt.u32.u64 %0, t; }"
               : "=r"(a) : "l"(p));
    return a;
}

#define LDSM_X4(rr, addr) \
    asm volatile("ldmatrix.sync.aligned.m8n8.x4.shared.b16 {%0,%1,%2,%3}, [%4];" \
        : "=r"((rr)[0]), "=r"((rr)[1]), "=r"((rr)[2]), "=r"((rr)[3]) : "r"(addr))

__device__ __forceinline__ void mma16816(float* d, const u32* a, const u32* b) {
    asm volatile(
        "mma.sync.aligned.m16n8k16.row.col.f32.bf16.bf16.f32 "
        "{%0,%1,%2,%3}, {%4,%5,%6,%7}, {%8,%9}, {%0,%1,%2,%3};"
        : "+f"(d[0]), "+f"(d[1]), "+f"(d[2]), "+f"(d[3])
        : "r"(a[0]), "r"(a[1]), "r"(a[2]), "r"(a[3]), "r"(b[0]), "r"(b[1]));
}

__device__ __forceinline__ void cp16(u32 smem_dst, const void* gsrc) {
    asm volatile("cp.async.cg.shared.global [%0], [%1], 16;"
                 :: "r"(smem_dst), "l"(gsrc) : "memory");
}
#define CP_COMMIT() asm volatile("cp.async.commit_group;" ::: "memory")
#define CP_WAIT0()  asm volatile("cp.async.wait_group 0;" ::: "memory")

// fp32 pair -> bf16 hi pair (truncate, via PRMT) + bf16 lo pair (residual, rn).
__device__ __forceinline__ void split2(float x0, float x1, u32& h2, u32& l2) {
    const u32 b0 = __float_as_uint(x0), b1 = __float_as_uint(x1);
    asm("prmt.b32 %0, %1, %2, 0x7632;" : "=r"(h2) : "r"(b0), "r"(b1));
    const float lf0 = x0 - __uint_as_float(b0 & 0xFFFF0000u);
    const float lf1 = x1 - __uint_as_float(b1 & 0xFFFF0000u);
    __nv_bfloat162 t = __float22bfloat162_rn(make_float2(lf0, lf1));
    l2 = *reinterpret_cast<u32*>(&t);
}
// Two float4 (8 consecutive k) -> uint4 hi + uint4 lo (16B each).
__device__ __forceinline__ void split_f4x2(const float4 v0, const float4 v1,
                                           uint4& H, uint4& L) {
    split2(v0.x, v0.y, H.x, L.x);
    split2(v0.z, v0.w, H.y, L.y);
    split2(v1.x, v1.y, H.z, L.z);
    split2(v1.z, v1.w, H.w, L.w);
}

// =====================================================================
// prep_w: split W_s / W_t into bf16 hi/lo, stored pre-swizzled per 64-k
// chunk (exact SMEM tile image). grid = (8 chunks, 2 z), 256 threads.
// =====================================================================
__global__ __launch_bounds__(256) void prep_w_kernel(
    const float* __restrict__ W_s, const float* __restrict__ W_t)
{
    const int c = blockIdx.x, z = blockIdx.y;
    const float* __restrict__ W = z ? W_t : W_s;
    const int tid = threadIdx.x;
    #pragma unroll
    for (int r = 0; r < 4; r++) {
        const int pu = tid + r * 256;     // 0..1023 pair-units
        const int row = pu >> 3;          // 0..127
        const int qq = (pu & 7) << 1;     // even float4 index 0..14
        const float* p = W + (size_t)row * HID + c * 64 + (qq << 2);
        const float4 v0 = *reinterpret_cast<const float4*>(p);
        const float4 v1 = *reinterpret_cast<const float4*>(p + 4);
        uint4 H, L; split_f4x2(v0, v1, H, L);
        const u32 off = (u32)(row * 128 + 16 * ((pu & 7) ^ (row & 7)));
        *reinterpret_cast<uint4*>(&g_wh[z][c][off]) = H;
        *reinterpret_cast<uint4*>(&g_wl[z][c][off]) = L;
    }
}

// =====================================================================
// HMMA projection: C[m][n] = sum_h X[m][h] * W[n][h]  (+ bias if z)
// CTA: 128 m x 128 n; K-chunks of 64; bf16 hi/lo split, 3 passes.
// 8 warps = 4m x 2n, warp tile 32x64, mma.m16n8k16.
// A: reg-pipelined LDG + PRMT split + STS.128. B: cp.async of precomputed
// swizzled tiles. grid = (64 m-tiles, 2 [enc|dec]), 256 threads.
// =====================================================================
#define PSM_AH 0
#define PSM_AL 16384
#define PSM_BH 32768
#define PSM_BL 49152
#define PSM_TOTAL 65536

__global__ __launch_bounds__(256) void proj_mma_kernel(
    const float* __restrict__ dec_out,
    const float* __restrict__ enc_outs,
    const float* __restrict__ b_t)
{
    extern __shared__ char smem[];
    const u32 sb = smem_u32(smem);
    const u32 AHs = sb + PSM_AH, ALs = sb + PSM_AL;
    const u32 BHs = sb + PSM_BH, BLs = sb + PSM_BL;

    const int tid = threadIdx.x;
    const int wid = tid >> 5;
    const int lane = tid & 31;
    const int z = blockIdx.y;
    const float* __restrict__ X = z ? dec_out : enc_outs;
    float* __restrict__ C = z ? g_dec_att : g_enc_att;
    const int m0 = blockIdx.x * 128;

    // ldmatrix lane geometry
    const int j = lane >> 3;
    const int r = lane & 7;
    const int wm = wid & 3;
    const int wn = wid >> 2;

    const int rowA0 = wm * 32 + ((j & 1) << 3) + r;
    const int rowA1 = rowA0 + 16;
    const u32 offA0 = rowA0 * 128, cxA0 = (rowA0 & 7) * 16;
    const u32 offA1 = rowA1 * 128, cxA1 = (rowA1 & 7) * 16;
    const u32 kbAj = (u32)((j >> 1) << 4);

    u32 offB[4], cxB[4];
    #pragma unroll
    for (int p = 0; p < 4; p++) {
        const int nrow = wn * 64 + p * 16 + ((j >> 1) << 3) + r;
        offB[p] = nrow * 128;
        cxB[p]  = (nrow & 7) * 16;
    }
    const u32 kbBj = (u32)((j & 1) << 4);

    float d[2][8][4];
    #pragma unroll
    for (int mf = 0; mf < 2; mf++)
        #pragma unroll
        for (int nf = 0; nf < 8; nf++)
            #pragma unroll
            for (int q = 0; q < 4; q++) d[mf][nf][q] = 0.f;

    // Preload A raw values for chunk 0.
    float4 areg[8];
    #pragma unroll
    for (int rr = 0; rr < 4; rr++) {
        const int pu = tid + rr * 256;
        const int row = pu >> 3;
        const int qq = (pu & 7) << 1;
        const float* p = X + (size_t)(m0 + row) * HID + (qq << 2);
        areg[2 * rr]     = *reinterpret_cast<const float4*>(p);
        areg[2 * rr + 1] = *reinterpret_cast<const float4*>(p + 4);
    }

    for (int c = 0; c < 8; c++) {
        __syncthreads();   // previous chunk's ldmatrix done before refill

        // B: async copy of precomputed swizzled tiles.
        {
            const unsigned char* sh = g_wh[z][c];
            const unsigned char* sl = g_wl[z][c];
            #pragma unroll
            for (int rr = 0; rr < 4; rr++) {
                const u32 off = (u32)((tid + rr * 256) << 4);
                cp16(BHs + off, sh + off);
                cp16(BLs + off, sl + off);
            }
            CP_COMMIT();
        }
        // A: convert preloaded regs, STS.128.
        #pragma unroll
        for (int rr = 0; rr < 4; rr++) {
            const int pu = tid + rr * 256;
            const int row = pu >> 3;
            uint4 H, L; split_f4x2(areg[2 * rr], areg[2 * rr + 1], H, L);
            const u32 off = (u32)(row * 128 + 16 * ((pu & 7) ^ (row & 7)));
            *reinterpret_cast<uint4*>(smem + PSM_AH + off) = H;
            *reinterpret_cast<uint4*>(smem + PSM_AL + off) = L;
        }
        // Preload next chunk's A (LDG latency hidden under the mma below).
        if (c < 7) {
            const int k0n = (c + 1) * 64;
            #pragma unroll
            for (int rr = 0; rr < 4; rr++) {
                const int pu = tid + rr * 256;
                const int row = pu >> 3;
                const int qq = (pu & 7) << 1;
                const float* p = X + (size_t)(m0 + row) * HID + k0n + (qq << 2);
                areg[2 * rr]     = *reinterpret_cast<const float4*>(p);
                areg[2 * rr + 1] = *reinterpret_cast<const float4*>(p + 4);
            }
        }
        CP_WAIT0();
        __syncthreads();

        #pragma unroll
        for (int kk = 0; kk < 4; kk++) {
            const u32 kbA = (u32)(kk * 32) + kbAj;
            const u32 kbB = (u32)(kk * 32) + kbBj;

            u32 ah0[4], ah1[4], al0[4], al1[4];
            LDSM_X4(ah0, AHs + offA0 + (kbA ^ cxA0));
            LDSM_X4(ah1, AHs + offA1 + (kbA ^ cxA1));
            LDSM_X4(al0, ALs + offA0 + (kbA ^ cxA0));
            LDSM_X4(al1, ALs + offA1 + (kbA ^ cxA1));

            u32 bb[4][4];
            #pragma unroll
            for (int p = 0; p < 4; p++)
                LDSM_X4(bb[p], BHs + offB[p] + (kbB ^ cxB[p]));
            #pragma unroll
            for (int p = 0; p < 4; p++) {
                // hh pass
                mma16816(d[0][2 * p],     ah0, &bb[p][0]);
                mma16816(d[0][2 * p + 1], ah0, &bb[p][2]);
                mma16816(d[1][2 * p],     ah1, &bb[p][0]);
                mma16816(d[1][2 * p + 1], ah1, &bb[p][2]);
                // lh pass (A_lo x B_hi)
                mma16816(d[0][2 * p],     al0, &bb[p][0]);
                mma16816(d[0][2 * p + 1], al0, &bb[p][2]);
                mma16816(d[1][2 * p],     al1, &bb[p][0]);
                mma16816(d[1][2 * p + 1], al1, &bb[p][2]);
            }
            #pragma unroll
            for (int p = 0; p < 4; p++)
                LDSM_X4(bb[p], BLs + offB[p] + (kbB ^ cxB[p]));
            #pragma unroll
            for (int p = 0; p < 4; p++) {
                // hl pass (A_hi x B_lo)
                mma16816(d[0][2 * p],     ah0, &bb[p][0]);
                mma16816(d[0][2 * p + 1], ah0, &bb[p][2]);
                mma16816(d[1][2 * p],     ah1, &bb[p][0]);
                mma16816(d[1][2 * p + 1], ah1, &bb[p][2]);
            }
        }
    }

    // Epilogue: C frag (m16n8): c0,c1 -> row = lane/4, cols (lane%4)*2 +{0,1};
    // c2,c3 -> row+8. Add bias for dec, float2 stores.
    const int er = lane >> 2;
    const int ec = (lane & 3) << 1;
    float bias[8][2];
    #pragma unroll
    for (int nf = 0; nf < 8; nf++) {
        const int col = wn * 64 + nf * 8 + ec;
        bias[nf][0] = z ? b_t[col] : 0.f;
        bias[nf][1] = z ? b_t[col + 1] : 0.f;
    }
    #pragma unroll
    for (int mf = 0; mf < 2; mf++) {
        const int row = m0 + wm * 32 + mf * 16 + er;
        #pragma unroll
        for (int nf = 0; nf < 8; nf++) {
            const int col = wn * 64 + nf * 8 + ec;
            float2 v0; v0.x = d[mf][nf][0] + bias[nf][0]; v0.y = d[mf][nf][1] + bias[nf][1];
            *reinterpret_cast<float2*>(C + (size_t)row * ATT + col) = v0;
            float2 v1; v1.x = d[mf][nf][2] + bias[nf][0]; v1.y = d[mf][nf][3] + bias[nf][1];
            *reinterpret_cast<float2*>(C + (size_t)(row + 8) * ATT + col) = v1;
        }
    }
}

// =====================================================================
// Score kernel (f32, at MUFU element roofline):
// out[t][b][s] = sum_a v[a] * tanh(dec_att[t,b,a] + enc_att[s,b,a])
// =====================================================================
__device__ __forceinline__ float tanh_fast(float x) {
    float y;
    asm("tanh.approx.f32 %0, %1;" : "=f"(y) : "f"(x));
    return y;
}

__global__ __launch_bounds__(256) void score_kernel(
    const float* __restrict__ v_a,
    float* __restrict__ out)
{
    __shared__ float sh_e[ATT][33];
    __shared__ float sh_d[ATT][33];
    __shared__ float sh_v[ATT];

    const int tid = threadIdx.x;
    const int b = blockIdx.z;
    const int s_base = blockIdx.x * 32;
    const int t_base = blockIdx.y * 32;

    for (int idx = tid; idx < 32 * 32; idx += 256) {
        const int i  = idx >> 5;
        const int a4 = idx & 31;
        const float4 ev = *reinterpret_cast<const float4*>(
            g_enc_att + ((size_t)(s_base + i) * BATCH + b) * ATT + (a4 << 2));
        sh_e[a4 * 4 + 0][i] = ev.x;
        sh_e[a4 * 4 + 1][i] = ev.y;
        sh_e[a4 * 4 + 2][i] = ev.z;
        sh_e[a4 * 4 + 3][i] = ev.w;
        const float4 dv = *reinterpret_cast<const float4*>(
            g_dec_att + ((size_t)(t_base + i) * BATCH + b) * ATT + (a4 << 2));
        sh_d[a4 * 4 + 0][i] = dv.x;
        sh_d[a4 * 4 + 1][i] = dv.y;
        sh_d[a4 * 4 + 2][i] = dv.z;
        sh_d[a4 * 4 + 3][i] = dv.w;
    }
    if (tid < ATT) sh_v[tid] = v_a[tid];
    __syncthreads();

    const int tx = tid & 15;
    const int ty = tid >> 4;
    const int sl = tx << 1;
    const int tl = ty << 1;

    float acc00 = 0.f, acc01 = 0.f, acc10 = 0.f, acc11 = 0.f;

    #pragma unroll 4
    for (int a = 0; a < ATT; a++) {
        const float va = sh_v[a];
        const float e0 = sh_e[a][sl];
        const float e1 = sh_e[a][sl + 1];
        const float d0 = sh_d[a][tl];
        const float d1 = sh_d[a][tl + 1];
        acc00 = fmaf(va, tanh_fast(d0 + e0), acc00);
        acc01 = fmaf(va, tanh_fast(d0 + e1), acc01);
        acc10 = fmaf(va, tanh_fast(d1 + e0), acc10);
        acc11 = fmaf(va, tanh_fast(d1 + e1), acc11);
    }

    const int tg = t_base + tl;
    const int sg = s_base + sl;
    float* o0 = out + ((size_t)tg * BATCH + b) * SRC_LEN + sg;
    float2 r0; r0.x = acc00; r0.y = acc01;
    *reinterpret_cast<float2*>(o0) = r0;
    float* o1 = o0 + (size_t)BATCH * SRC_LEN;
    float2 r1; r1.x = acc10; r1.y = acc11;
    *reinterpret_cast<float2*>(o1) = r1;
}

extern "C" void kernel_launch(void* const* d_in, const int* in_sizes, int n_in,
                              void* d_out, int out_size)
{
    const float* dec_out  = (const float*)d_in[0];  // (256, 32, 512)
    const float* enc_outs = (const float*)d_in[1];  // (256, 32, 512)
    const float* W_s      = (const float*)d_in[2];  // (128, 512)
    const float* W_t      = (const float*)d_in[3];  // (128, 512)
    const float* b_t      = (const float*)d_in[4];  // (128,)
    const float* v_a      = (const float*)d_in[5];  // (128, 1)
    float* out = (float*)d_out;                     // (256, 32, 256)

    (void)in_sizes; (void)n_in; (void)out_size;

    cudaFuncSetAttribute(proj_mma_kernel,
                         cudaFuncAttributeMaxDynamicSharedMemorySize, PSM_TOTAL);

    prep_w_kernel<<<dim3(8, 2), 256>>>(W_s, W_t);
    proj_mma_kernel<<<dim3(64, 2), 256, PSM_TOTAL>>>(dec_out, enc_outs, b_t);
    score_kernel<<<dim3(SRC_LEN / 32, TRG_LEN / 32, BATCH), 256>>>(v_a, out);
}

// round 9
// speedup vs baseline: 3.1873x; 1.0206x over previous
#include <cuda_runtime.h>
#include <cuda_bf16.h>
#include <cuda_fp16.h>
#include <cstdint>

#define SRC_LEN 256
#define TRG_LEN 256
#define BATCH   32
#define HID     512
#define ATT     128

// Scratch for projected activations. Layout: [(len_idx * BATCH + b) * ATT + a]
__device__ float g_enc_att[SRC_LEN * BATCH * ATT];
__device__ float g_dec_att[TRG_LEN * BATCH * ATT];

// Precomputed, pre-swizzled bf16 hi/lo W tiles: [z][chunk][16KB tile]
__device__ __align__(16) unsigned char g_wh[2][8][16384];
__device__ __align__(16) unsigned char g_wl[2][8][16384];

typedef unsigned int u32;
typedef unsigned long long u64;

__device__ __forceinline__ u32 smem_u32(const void* p) {
    u32 a; asm("{ .reg .u64 t; cvta.to.shared.u64 t, %1; cvt.u32.u64 %0, t; }"
               : "=r"(a) : "l"(p));
    return a;
}

#define LDSM_X4(rr, addr) \
    asm volatile("ldmatrix.sync.aligned.m8n8.x4.shared.b16 {%0,%1,%2,%3}, [%4];" \
        : "=r"((rr)[0]), "=r"((rr)[1]), "=r"((rr)[2]), "=r"((rr)[3]) : "r"(addr))

__device__ __forceinline__ void mma16816(float* d, const u32* a, const u32* b) {
    asm volatile(
        "mma.sync.aligned.m16n8k16.row.col.f32.bf16.bf16.f32 "
        "{%0,%1,%2,%3}, {%4,%5,%6,%7}, {%8,%9}, {%0,%1,%2,%3};"
        : "+f"(d[0]), "+f"(d[1]), "+f"(d[2]), "+f"(d[3])
        : "r"(a[0]), "r"(a[1]), "r"(a[2]), "r"(a[3]), "r"(b[0]), "r"(b[1]));
}

__device__ __forceinline__ void cp16(u32 smem_dst, const void* gsrc) {
    asm volatile("cp.async.cg.shared.global [%0], [%1], 16;"
                 :: "r"(smem_dst), "l"(gsrc) : "memory");
}
#define CP_COMMIT()  asm volatile("cp.async.commit_group;" ::: "memory")
#define CP_WAIT(n)   asm volatile("cp.async.wait_group %0;" :: "n"(n) : "memory")

// fp32 pair -> bf16 hi pair (truncate, via PRMT) + bf16 lo pair (residual, rn).
__device__ __forceinline__ void split2(float x0, float x1, u32& h2, u32& l2) {
    const u32 b0 = __float_as_uint(x0), b1 = __float_as_uint(x1);
    asm("prmt.b32 %0, %1, %2, 0x7632;" : "=r"(h2) : "r"(b0), "r"(b1));
    const float lf0 = x0 - __uint_as_float(b0 & 0xFFFF0000u);
    const float lf1 = x1 - __uint_as_float(b1 & 0xFFFF0000u);
    __nv_bfloat162 t = __float22bfloat162_rn(make_float2(lf0, lf1));
    l2 = *reinterpret_cast<u32*>(&t);
}
__device__ __forceinline__ void split_f4x2(const float4 v0, const float4 v1,
                                           uint4& H, uint4& L) {
    split2(v0.x, v0.y, H.x, L.x);
    split2(v0.z, v0.w, H.y, L.y);
    split2(v1.x, v1.y, H.z, L.z);
    split2(v1.z, v1.w, H.w, L.w);
}

// =====================================================================
// prep_w: split W_s / W_t into bf16 hi/lo, stored pre-swizzled per 64-k
// chunk. grid = (32 [chunk*4+slice], 2 z), 256 threads, 1 unit each.
// =====================================================================
__global__ __launch_bounds__(256) void prep_w_kernel(
    const float* __restrict__ W_s, const float* __restrict__ W_t)
{
    const int c = blockIdx.x >> 2;
    const int slice = blockIdx.x & 3;
    const int z = blockIdx.y;
    const float* __restrict__ W = z ? W_t : W_s;
    const int pu = slice * 256 + threadIdx.x;   // 0..1023 pair-units
    const int row = pu >> 3;                    // 0..127
    const int qq = (pu & 7) << 1;               // even float4 index
    const float* p = W + (size_t)row * HID + c * 64 + (qq << 2);
    const float4 v0 = *reinterpret_cast<const float4*>(p);
    const float4 v1 = *reinterpret_cast<const float4*>(p + 4);
    uint4 H, L; split_f4x2(v0, v1, H, L);
    const u32 off = (u32)(row * 128 + 16 * ((pu & 7) ^ (row & 7)));
    *reinterpret_cast<uint4*>(&g_wh[z][c][off]) = H;
    *reinterpret_cast<uint4*>(&g_wl[z][c][off]) = L;
}

// =====================================================================
// HMMA projection: C[m][n] = sum_h X[m][h] * W[n][h]  (+ bias if z)
// CTA: 128 m x 128 n; K-chunks of 64; bf16 hi/lo split, 3 passes.
// 8 warps = 4m x 2n, warp tile 32x64, mma.m16n8k16.
// A: reg-pipelined LDG + PRMT split + STS.128.
// B: 2-stage double-buffered cp.async of precomputed swizzled tiles —
//    B(c+1) flies under mma(c).
// grid = (64 m-tiles, 2 [enc|dec]), 256 threads, 96KB dynamic smem.
// =====================================================================
#define PSM_AH 0
#define PSM_AL 16384
#define PSM_B  32768          // stage s: BH @ PSM_B + s*32768, BL = BH + 16384
#define PSM_TOTAL 98304

__global__ __launch_bounds__(256) void proj_mma_kernel(
    const float* __restrict__ dec_out,
    const float* __restrict__ enc_outs,
    const float* __restrict__ b_t)
{
    extern __shared__ char smem[];
    const u32 sb = smem_u32(smem);
    const u32 AHs = sb + PSM_AH, ALs = sb + PSM_AL;

    const int tid = threadIdx.x;
    const int wid = tid >> 5;
    const int lane = tid & 31;
    const int z = blockIdx.y;
    const float* __restrict__ X = z ? dec_out : enc_outs;
    float* __restrict__ C = z ? g_dec_att : g_enc_att;
    const int m0 = blockIdx.x * 128;

    // ldmatrix lane geometry
    const int j = lane >> 3;
    const int r = lane & 7;
    const int wm = wid & 3;
    const int wn = wid >> 2;

    const int rowA0 = wm * 32 + ((j & 1) << 3) + r;
    const int rowA1 = rowA0 + 16;
    const u32 offA0 = rowA0 * 128, cxA0 = (rowA0 & 7) * 16;
    const u32 offA1 = rowA1 * 128, cxA1 = (rowA1 & 7) * 16;
    const u32 kbAj = (u32)((j >> 1) << 4);

    u32 offB[4], cxB[4];
    #pragma unroll
    for (int p = 0; p < 4; p++) {
        const int nrow = wn * 64 + p * 16 + ((j >> 1) << 3) + r;
        offB[p] = nrow * 128;
        cxB[p]  = (nrow & 7) * 16;
    }
    const u32 kbBj = (u32)((j & 1) << 4);

    float d[2][8][4];
    #pragma unroll
    for (int mf = 0; mf < 2; mf++)
        #pragma unroll
        for (int nf = 0; nf < 8; nf++)
            #pragma unroll
            for (int q = 0; q < 4; q++) d[mf][nf][q] = 0.f;

    // Issue B(0) copy into stage 0.
    {
        const unsigned char* sh = g_wh[z][0];
        const unsigned char* sl = g_wl[z][0];
        #pragma unroll
        for (int rr = 0; rr < 4; rr++) {
            const u32 off = (u32)((tid + rr * 256) << 4);
            cp16(sb + PSM_B + off, sh + off);
            cp16(sb + PSM_B + 16384 + off, sl + off);
        }
        CP_COMMIT();
    }
    // Preload A raw values for chunk 0.
    float4 areg[8];
    #pragma unroll
    for (int rr = 0; rr < 4; rr++) {
        const int pu = tid + rr * 256;
        const int row = pu >> 3;
        const int qq = (pu & 7) << 1;
        const float* p = X + (size_t)(m0 + row) * HID + (qq << 2);
        areg[2 * rr]     = *reinterpret_cast<const float4*>(p);
        areg[2 * rr + 1] = *reinterpret_cast<const float4*>(p + 4);
    }

    for (int c = 0; c < 8; c++) {
        __syncthreads();   // chunk c-1 ldmatrix done: A smem + B stage (c+1)&1 free

        // A: convert preloaded regs, STS.128.
        #pragma unroll
        for (int rr = 0; rr < 4; rr++) {
            const int pu = tid + rr * 256;
            const int row = pu >> 3;
            uint4 H, L; split_f4x2(areg[2 * rr], areg[2 * rr + 1], H, L);
            const u32 off = (u32)(row * 128 + 16 * ((pu & 7) ^ (row & 7)));
            *reinterpret_cast<uint4*>(smem + PSM_AH + off) = H;
            *reinterpret_cast<uint4*>(smem + PSM_AL + off) = L;
        }
        if (c < 7) {
            // Issue B(c+1) into the other stage (flies under mma below).
            const u32 bs = sb + PSM_B + ((c + 1) & 1) * 32768;
            const unsigned char* sh = g_wh[z][c + 1];
            const unsigned char* sl = g_wl[z][c + 1];
            #pragma unroll
            for (int rr = 0; rr < 4; rr++) {
                const u32 off = (u32)((tid + rr * 256) << 4);
                cp16(bs + off, sh + off);
                cp16(bs + 16384 + off, sl + off);
            }
            CP_COMMIT();
            // Preload next chunk's A (LDG latency hidden under mma below).
            const int k0n = (c + 1) * 64;
            #pragma unroll
            for (int rr = 0; rr < 4; rr++) {
                const int pu = tid + rr * 256;
                const int row = pu >> 3;
                const int qq = (pu & 7) << 1;
                const float* p = X + (size_t)(m0 + row) * HID + k0n + (qq << 2);
                areg[2 * rr]     = *reinterpret_cast<const float4*>(p);
                areg[2 * rr + 1] = *reinterpret_cast<const float4*>(p + 4);
            }
            CP_WAIT(1);    // B(c) done; B(c+1) still in flight
        } else {
            CP_WAIT(0);    // last chunk: B(7) done
        }
        __syncthreads();

        const u32 BHs = sb + PSM_B + (c & 1) * 32768;
        const u32 BLs = BHs + 16384;

        #pragma unroll
        for (int kk = 0; kk < 4; kk++) {
            const u32 kbA = (u32)(kk * 32) + kbAj;
            const u32 kbB = (u32)(kk * 32) + kbBj;

            u32 ah0[4], ah1[4], al0[4], al1[4];
            LDSM_X4(ah0, AHs + offA0 + (kbA ^ cxA0));
            LDSM_X4(ah1, AHs + offA1 + (kbA ^ cxA1));
            LDSM_X4(al0, ALs + offA0 + (kbA ^ cxA0));
            LDSM_X4(al1, ALs + offA1 + (kbA ^ cxA1));

            u32 bb[4][4];
            #pragma unroll
            for (int p = 0; p < 4; p++)
                LDSM_X4(bb[p], BHs + offB[p] + (kbB ^ cxB[p]));
            #pragma unroll
            for (int p = 0; p < 4; p++) {
                // hh pass
                mma16816(d[0][2 * p],     ah0, &bb[p][0]);
                mma16816(d[0][2 * p + 1], ah0, &bb[p][2]);
                mma16816(d[1][2 * p],     ah1, &bb[p][0]);
                mma16816(d[1][2 * p + 1], ah1, &bb[p][2]);
                // lh pass (A_lo x B_hi)
                mma16816(d[0][2 * p],     al0, &bb[p][0]);
                mma16816(d[0][2 * p + 1], al0, &bb[p][2]);
                mma16816(d[1][2 * p],     al1, &bb[p][0]);
                mma16816(d[1][2 * p + 1], al1, &bb[p][2]);
            }
            #pragma unroll
            for (int p = 0; p < 4; p++)
                LDSM_X4(bb[p], BLs + offB[p] + (kbB ^ cxB[p]));
            #pragma unroll
            for (int p = 0; p < 4; p++) {
                // hl pass (A_hi x B_lo)
                mma16816(d[0][2 * p],     ah0, &bb[p][0]);
                mma16816(d[0][2 * p + 1], ah0, &bb[p][2]);
                mma16816(d[1][2 * p],     ah1, &bb[p][0]);
                mma16816(d[1][2 * p + 1], ah1, &bb[p][2]);
            }
        }
    }

    // Epilogue: C frag (m16n8): c0,c1 -> row = lane/4, cols (lane%4)*2 +{0,1};
    // c2,c3 -> row+8. Add bias for dec, float2 stores.
    const int er = lane >> 2;
    const int ec = (lane & 3) << 1;
    float bias[8][2];
    #pragma unroll
    for (int nf = 0; nf < 8; nf++) {
        const int col = wn * 64 + nf * 8 + ec;
        bias[nf][0] = z ? b_t[col] : 0.f;
        bias[nf][1] = z ? b_t[col + 1] : 0.f;
    }
    #pragma unroll
    for (int mf = 0; mf < 2; mf++) {
        const int row = m0 + wm * 32 + mf * 16 + er;
        #pragma unroll
        for (int nf = 0; nf < 8; nf++) {
            const int col = wn * 64 + nf * 8 + ec;
            float2 v0; v0.x = d[mf][nf][0] + bias[nf][0]; v0.y = d[mf][nf][1] + bias[nf][1];
            *reinterpret_cast<float2*>(C + (size_t)row * ATT + col) = v0;
            float2 v1; v1.x = d[mf][nf][2] + bias[nf][0]; v1.y = d[mf][nf][3] + bias[nf][1];
            *reinterpret_cast<float2*>(C + (size_t)(row + 8) * ATT + col) = v1;
        }
    }
}

// =====================================================================
// Score kernel (f32, at MUFU element roofline):
// out[t][b][s] = sum_a v[a] * tanh(dec_att[t,b,a] + enc_att[s,b,a])
// =====================================================================
__device__ __forceinline__ float tanh_fast(float x) {
    float y;
    asm("tanh.approx.f32 %0, %1;" : "=f"(y) : "f"(x));
    return y;
}

__global__ __launch_bounds__(256) void score_kernel(
    const float* __restrict__ v_a,
    float* __restrict__ out)
{
    __shared__ float sh_e[ATT][33];
    __shared__ float sh_d[ATT][33];
    __shared__ float sh_v[ATT];

    const int tid = threadIdx.x;
    const int b = blockIdx.z;
    const int s_base = blockIdx.x * 32;
    const int t_base = blockIdx.y * 32;

    for (int idx = tid; idx < 32 * 32; idx += 256) {
        const int i  = idx >> 5;
        const int a4 = idx & 31;
        const float4 ev = *reinterpret_cast<const float4*>(
            g_enc_att + ((size_t)(s_base + i) * BATCH + b) * ATT + (a4 << 2));
        sh_e[a4 * 4 + 0][i] = ev.x;
        sh_e[a4 * 4 + 1][i] = ev.y;
        sh_e[a4 * 4 + 2][i] = ev.z;
        sh_e[a4 * 4 + 3][i] = ev.w;
        const float4 dv = *reinterpret_cast<const float4*>(
            g_dec_att + ((size_t)(t_base + i) * BATCH + b) * ATT + (a4 << 2));
        sh_d[a4 * 4 + 0][i] = dv.x;
        sh_d[a4 * 4 + 1][i] = dv.y;
        sh_d[a4 * 4 + 2][i] = dv.z;
        sh_d[a4 * 4 + 3][i] = dv.w;
    }
    if (tid < ATT) sh_v[tid] = v_a[tid];
    __syncthreads();

    const int tx = tid & 15;
    const int ty = tid >> 4;
    const int sl = tx << 1;
    const int tl = ty << 1;

    float acc00 = 0.f, acc01 = 0.f, acc10 = 0.f, acc11 = 0.f;

    #pragma unroll 4
    for (int a = 0; a < ATT; a++) {
        const float va = sh_v[a];
        const float e0 = sh_e[a][sl];
        const float e1 = sh_e[a][sl + 1];
        const float d0 = sh_d[a][tl];
        const float d1 = sh_d[a][tl + 1];
        acc00 = fmaf(va, tanh_fast(d0 + e0), acc00);
        acc01 = fmaf(va, tanh_fast(d0 + e1), acc01);
        acc10 = fmaf(va, tanh_fast(d1 + e0), acc10);
        acc11 = fmaf(va, tanh_fast(d1 + e1), acc11);
    }

    const int tg = t_base + tl;
    const int sg = s_base + sl;
    float* o0 = out + ((size_t)tg * BATCH + b) * SRC_LEN + sg;
    float2 r0; r0.x = acc00; r0.y = acc01;
    *reinterpret_cast<float2*>(o0) = r0;
    float* o1 = o0 + (size_t)BATCH * SRC_LEN;
    float2 r1; r1.x = acc10; r1.y = acc11;
    *reinterpret_cast<float2*>(o1) = r1;
}

extern "C" void kernel_launch(void* const* d_in, const int* in_sizes, int n_in,
                              void* d_out, int out_size)
{
    const float* dec_out  = (const float*)d_in[0];  // (256, 32, 512)
    const float* enc_outs = (const float*)d_in[1];  // (256, 32, 512)
    const float* W_s      = (const float*)d_in[2];  // (128, 512)
    const float* W_t      = (const float*)d_in[3];  // (128, 512)
    const float* b_t      = (const float*)d_in[4];  // (128,)
    const float* v_a      = (const float*)d_in[5];  // (128, 1)
    float* out = (float*)d_out;                     // (256, 32, 256)

    (void)in_sizes; (void)n_in; (void)out_size;

    cudaFuncSetAttribute(proj_mma_kernel,
                         cudaFuncAttributeMaxDynamicSharedMemorySize, PSM_TOTAL);

    prep_w_kernel<<<dim3(32, 2), 256>>>(W_s, W_t);
    proj_mma_kernel<<<dim3(64, 2), 256, PSM_TOTAL>>>(dec_out, enc_outs, b_t);
    score_kernel<<<dim3(SRC_LEN / 32, TRG_LEN / 32, BATCH), 256>>>(v_a, out);
}